// round 1
// baseline (speedup 1.0000x reference)
#include <cuda_runtime.h>
#include <cstddef>

// x: (8, 16, 3, 256, 256) fp32 contiguous
// out: (128, 2, 256, 256) fp32
// out[bl, ch, hw] = x[bl*3 plane, hw] - x[(bl-1)*3 plane, hw]  if (bl % 16) != 0 else 0
//
// Vectorized float4: HW4 = 65536/4 = 16384 float4 per plane.

static constexpr int HW4 = 16384;         // 256*256/4
static constexpr int BL  = 128;           // 8*16
static constexpr int TOTAL4 = BL * HW4;   // 2,097,152 float4 threads

__global__ __launch_bounds__(256) void dummyflow_diff_kernel(
    const float4* __restrict__ x, float4* __restrict__ out)
{
    int idx = blockIdx.x * blockDim.x + threadIdx.x;
    if (idx >= TOTAL4) return;

    int bl = idx >> 14;         // idx / HW4
    int hw = idx & (HW4 - 1);   // idx % HW4
    int l  = bl & 15;

    float4 v;
    if (l == 0) {
        v = make_float4(0.f, 0.f, 0.f, 0.f);
    } else {
        // channel-0 plane of flattened (b,l) index bl is input plane bl*3
        size_t cur  = (size_t)(bl * 3)       * HW4 + hw;
        size_t prev = (size_t)((bl - 1) * 3) * HW4 + hw;
        float4 a = x[cur];
        float4 p = x[prev];
        v = make_float4(a.x - p.x, a.y - p.y, a.z - p.z, a.w - p.w);
    }

    // out plane stride: 2 channels per bl
    size_t o = (size_t)(bl * 2) * HW4 + hw;
    out[o]       = v;   // channel 0
    out[o + HW4] = v;   // channel 1
}

extern "C" void kernel_launch(void* const* d_in, const int* in_sizes, int n_in,
                              void* d_out, int out_size)
{
    const float4* x = (const float4*)d_in[0];
    float4* out = (float4*)d_out;

    int threads = 256;
    int blocks = (TOTAL4 + threads - 1) / threads;  // 8192
    dummyflow_diff_kernel<<<blocks, threads>>>(x, out);
}